// round 8
// baseline (speedup 1.0000x reference)
#include <cuda_runtime.h>
#include <cstdint>

#define K_DIM  8192
#define M_ROWS 128
#define N_COLS 8192
#define BM     128
#define BN     64
#define BK     128
#define NK     (K_DIM / BK)    // 64
#define NBUF   2
#define NTHR   512

// smem floats, per stage: x [h=2][128][64]; W [h=2][64][64]; A [h=2][8][64]
// rows of 64 floats, f4-xor swizzled (identical to R7 layout, replicated per half)
#define XSTG   (BM * BK)                      // 16384
#define WSTG   (BN * BK)                      // 8192
#define ASTG   (8 * BK)                       // 1024
#define XS_OFF 0
#define WS_OFF (NBUF * XSTG)                  // 32768
#define AS_OFF (WS_OFF + NBUF * WSTG)         // 49152
#define SMEM_FLOATS (AS_OFF + NBUF * ASTG)    // 51200 floats = 204800 B

__device__ float g_xt[M_ROWS * K_DIM];   // x, tf32-rounded (RN)

__device__ __forceinline__ uint32_t f2tf32(float f) {
    uint32_t u;
    asm("cvt.rna.tf32.f32 %0, %1;" : "=r"(u) : "f"(f));
    return u;
}

__device__ __forceinline__ uint32_t smem_u32(const void* p) {
    uint32_t a;
    asm("{ .reg .u64 t; cvta.to.shared.u64 t, %1; cvt.u32.u64 %0, t; }" : "=r"(a) : "l"(p));
    return a;
}

__device__ __forceinline__ void cp16(uint32_t dst, const void* src) {
    asm volatile("cp.async.cg.shared.global [%0], [%1], 16;" :: "r"(dst), "l"(src));
}

__device__ __forceinline__ void mma_tf32(float* d, const uint32_t* a, const uint32_t* b) {
    asm volatile(
        "mma.sync.aligned.m16n8k8.row.col.f32.tf32.tf32.f32 "
        "{%0,%1,%2,%3},{%4,%5,%6,%7},{%8,%9},{%0,%1,%2,%3};\n"
        : "+f"(d[0]), "+f"(d[1]), "+f"(d[2]), "+f"(d[3])
        : "r"(a[0]), "r"(a[1]), "r"(a[2]), "r"(a[3]), "r"(b[0]), "r"(b[1]));
}

__global__ void cvt_x_kernel(const float* __restrict__ x) {
    int i = blockIdx.x * blockDim.x + threadIdx.x;
    float4 v = reinterpret_cast<const float4*>(x)[i];
    uint4 o;
    o.x = f2tf32(v.x); o.y = f2tf32(v.y); o.z = f2tf32(v.z); o.w = f2tf32(v.w);
    reinterpret_cast<uint4*>(g_xt)[i] = o;
}

// out[m,n] = sum_k x[m,k]*W[n,k] + 2*s*B[n%16]*(x@A^T)[m, n/16]
__global__ __launch_bounds__(NTHR, 1)
void lokr_gemm_kernel(const float* __restrict__ Wm,
                      const float* __restrict__ Am,
                      const float* __restrict__ Bv,
                      const float* __restrict__ sc,
                      float* __restrict__ out)
{
    extern __shared__ float sm[];
    const uint32_t sb = smem_u32(sm);

    const int t    = threadIdx.x;
    const int lane = t & 31;
    const int warp = t >> 5;
    const int wm   = warp & 3;          // 4 m-warps, 32 rows each
    const int wn   = (warp >> 2) & 1;   // 2 n-warps, 32 cols each
    const int wk   = warp >> 3;         // 2 k-warps, one 64-col half each
    const int q    = lane & 3;
    const int g    = lane >> 2;
    const int n0   = blockIdx.x * BN;

    // zero A pad rows (4..7) in both halves of every stage, once
    for (int i = t; i < NBUF * 2 * 4 * 64; i += NTHR) {
        const int s = i >> 9, r2 = i & 511;
        const int h = r2 >> 8, r = (r2 >> 6) & 3, c = r2 & 63;
        sm[AS_OFF + s * ASTG + h * 512 + (4 + r) * 64 + c] = 0.0f;
    }

    // ---- fill geometry: 16 f4-chunks per 64-float row-half ----
    const int kq = t & 15;      // f4 column 0..15
    const int rr = t >> 4;      // row 0..31
    const uint32_t swb = (uint32_t)((kq ^ (rr & 7)) << 4);
    const float* wg = Wm + (size_t)(n0 + rr) * K_DIM + kq * 4;
    const float* xg = g_xt + (size_t)rr * K_DIM + kq * 4;
    const float* ag = Am + (size_t)(blockIdx.x * 4 + (rr & 3)) * K_DIM + kq * 4;

    // fill: pure cp.async (x tf32-RN; W raw fp32 -> HW-truncated tf32; A raw fp32)
    auto fill = [&](int f) {
        const int s = f & 1;
        const size_t ko = (size_t)f * BK;
        #pragma unroll
        for (int h = 0; h < 2; ++h) {
            #pragma unroll
            for (int j = 0; j < 4; ++j) {
                const uint32_t xd = sb + 4u * (XS_OFF + s * XSTG + h * 8192 + (j * 32 + rr) * 64) + swb;
                cp16(xd, xg + (size_t)(32 * j) * K_DIM + ko + h * 64);
            }
            #pragma unroll
            for (int jm = 0; jm < 2; ++jm) {
                const uint32_t wd = sb + 4u * (WS_OFF + s * WSTG + h * 4096 + (jm * 32 + rr) * 64) + swb;
                cp16(wd, wg + (size_t)(32 * jm) * K_DIM + ko + h * 64);
            }
            if (t < 64) {
                const int ar = rr & 3;
                const uint32_t ad = sb + 4u * (AS_OFF + s * ASTG + h * 512 + ar * 64 + ((kq ^ ar) << 2));
                cp16(ad, ag + ko + h * 64);
            }
        }
        asm volatile("cp.async.commit_group;");
    };

    fill(0);

    float acc[2][4][4];
    float yac[2][4];
    #pragma unroll
    for (int mt = 0; mt < 2; ++mt) {
        #pragma unroll
        for (int nt = 0; nt < 4; ++nt)
            #pragma unroll
            for (int r = 0; r < 4; ++r) acc[mt][nt][r] = 0.0f;
        #pragma unroll
        for (int r = 0; r < 4; ++r) yac[mt][r] = 0.0f;
    }

    // double-buffered fragment registers
    uint32_t afr[2][2][4];
    uint32_t bfr[2][4][2];
    uint32_t bex[2][2];

    for (int kt = 0; kt < NK; ++kt) {
        asm volatile("cp.async.wait_group 0;");
        __syncthreads();
        if (kt + 1 < NK) fill(kt + 1);   // lands during this stage's compute

        const int s = kt & 1;
        const float* xb = sm + XS_OFF + s * XSTG + wk * 8192;
        const float* wb = sm + WS_OFF + s * WSTG + wk * 4096;
        const float* ab = sm + AS_OFF + s * ASTG + wk * 512;

        auto ldfr = [&](int b, int kgl) {
            const int c0 = ((2 * kgl) ^ g) * 4 + q;
            const int c1 = ((2 * kgl + 1) ^ g) * 4 + q;
            #pragma unroll
            for (int mt = 0; mt < 2; ++mt) {
                const float* base = xb + (wm * 32 + mt * 16 + g) * 64;
                afr[b][mt][0] = __float_as_uint(base[c0]);
                afr[b][mt][1] = __float_as_uint(base[8 * 64 + c0]);
                afr[b][mt][2] = __float_as_uint(base[c1]);
                afr[b][mt][3] = __float_as_uint(base[8 * 64 + c1]);
            }
            #pragma unroll
            for (int nt = 0; nt < 4; ++nt) {
                const float* bp = wb + (wn * 32 + nt * 8 + g) * 64;
                bfr[b][nt][0] = __float_as_uint(bp[c0]);
                bfr[b][nt][1] = __float_as_uint(bp[c1]);
            }
            const float* ap = ab + g * 64;
            bex[b][0] = __float_as_uint(ap[c0]);
            bex[b][1] = __float_as_uint(ap[c1]);
        };

        ldfr(0, 0);
        #pragma unroll
        for (int kgl = 0; kgl < 8; ++kgl) {
            const int cur = kgl & 1;
            if (kgl < 7) ldfr(cur ^ 1, kgl + 1);   // overlaps the MMAs below
            #pragma unroll
            for (int mt = 0; mt < 2; ++mt) {
                #pragma unroll
                for (int nt = 0; nt < 4; ++nt)
                    mma_tf32(acc[mt][nt], afr[cur][mt], bfr[cur][nt]);
                mma_tf32(yac[mt], afr[cur][mt], bex[cur]);
            }
        }
        __syncthreads();
    }

    // ---- k-half reduction through smem scratch ----
    float* scr = sm;
    if (wk == 1) {
        const int pos = warp - 8;
        float* as_ = scr + pos * 1312 + lane * 41;
        #pragma unroll
        for (int mt = 0; mt < 2; ++mt)
            #pragma unroll
            for (int nt = 0; nt < 4; ++nt)
                #pragma unroll
                for (int r = 0; r < 4; ++r)
                    as_[(mt * 4 + nt) * 4 + r] = acc[mt][nt][r];
        #pragma unroll
        for (int mt = 0; mt < 2; ++mt)
            #pragma unroll
            for (int r = 0; r < 4; ++r)
                as_[32 + mt * 4 + r] = yac[mt][r];
    }
    __syncthreads();
    if (wk == 0) {
        const int pos = warp;
        const float* as_ = scr + pos * 1312 + lane * 41;
        #pragma unroll
        for (int mt = 0; mt < 2; ++mt)
            #pragma unroll
            for (int nt = 0; nt < 4; ++nt)
                #pragma unroll
                for (int r = 0; r < 4; ++r)
                    acc[mt][nt][r] += as_[(mt * 4 + nt) * 4 + r];
        #pragma unroll
        for (int mt = 0; mt < 2; ++mt)
            #pragma unroll
            for (int r = 0; r < 4; ++r)
                yac[mt][r] += as_[32 + mt * 4 + r];

        // ---- epilogue: out = acc + cf[n%16] * y[m, n/16] ----
        const float s2 = 2.0f * sc[0];
        const float cfe0 = s2 * Bv[2 * q];
        const float cfe1 = s2 * Bv[2 * q + 1];
        const float cfo0 = s2 * Bv[8 + 2 * q];
        const float cfo1 = s2 * Bv[9 + 2 * q];

        #pragma unroll
        for (int mt = 0; mt < 2; ++mt) {
            const int srcl = g * 4 + wn;
            const float yA0 = __shfl_sync(0xFFFFFFFFu, yac[mt][0], srcl);
            const float yA1 = __shfl_sync(0xFFFFFFFFu, yac[mt][1], srcl);
            const float yB0 = __shfl_sync(0xFFFFFFFFu, yac[mt][2], srcl);
            const float yB1 = __shfl_sync(0xFFFFFFFFu, yac[mt][3], srcl);
            #pragma unroll
            for (int nt = 0; nt < 4; ++nt) {
                const float yg  = (nt < 2) ? yA0 : yA1;
                const float yg8 = (nt < 2) ? yB0 : yB1;
                const float f0 = (nt & 1) ? cfo0 : cfe0;
                const float f1 = (nt & 1) ? cfo1 : cfe1;
                const int m = wm * 32 + mt * 16 + g;
                const int n = n0 + wn * 32 + nt * 8 + 2 * q;
                float2 v0 = make_float2(acc[mt][nt][0] + f0 * yg, acc[mt][nt][1] + f1 * yg);
                float2 v1 = make_float2(acc[mt][nt][2] + f0 * yg8, acc[mt][nt][3] + f1 * yg8);
                *reinterpret_cast<float2*>(out + (size_t)m * N_COLS + n) = v0;
                *reinterpret_cast<float2*>(out + (size_t)(m + 8) * N_COLS + n) = v1;
            }
        }
    }
}

extern "C" void kernel_launch(void* const* d_in, const int* in_sizes, int n_in,
                              void* d_out, int out_size) {
    const float* x  = (const float*)d_in[0];   // (128, 8192)
    const float* Wm = (const float*)d_in[1];   // (8192, 8192)
    const float* Am = (const float*)d_in[2];   // (512, 8192)
    const float* Bv = (const float*)d_in[3];   // (16, 1)
    const float* sc = (const float*)d_in[4];   // (1,)
    float* out = (float*)d_out;                // (128, 8192)

    cudaFuncSetAttribute(lokr_gemm_kernel,
                         cudaFuncAttributeMaxDynamicSharedMemorySize,
                         SMEM_FLOATS * 4);

    cvt_x_kernel<<<(M_ROWS * K_DIM / 4) / 256, 256>>>(x);
    lokr_gemm_kernel<<<N_COLS / BN, NTHR, SMEM_FLOATS * 4>>>(Wm, Am, Bv, sc, out);
}

// round 9
// speedup vs baseline: 1.2037x; 1.2037x over previous
#include <cuda_runtime.h>
#include <cstdint>

#define K_DIM  8192
#define KHALF  4096
#define M_ROWS 128
#define N_COLS 8192
#define BM     128
#define BN     128
#define BK     64
#define NKS    (KHALF / BK)    // 64 stages per CTA
#define NBUF   3
#define NTHR   512

// smem floats per stage: x [128][64]; W [128][64]; A [8][64]; f4-xor swizzled rows
#define XSTG   (BM * BK)                      // 8192
#define WSTG   (BN * BK)                      // 8192
#define ASTG   (8 * BK)                       // 512
#define XS_OFF 0
#define WS_OFF (NBUF * XSTG)                  // 24576
#define AS_OFF (WS_OFF + NBUF * WSTG)         // 49152
#define SMEM_FLOATS (AS_OFF + NBUF * ASTG)    // 50688 floats = 202752 B

__device__ float g_xt[M_ROWS * K_DIM];            // x, tf32-rounded (RN)
__device__ float g_part[2 * M_ROWS * N_COLS];     // split-K partials (8 MB)

__device__ __forceinline__ uint32_t f2tf32(float f) {
    uint32_t u;
    asm("cvt.rna.tf32.f32 %0, %1;" : "=r"(u) : "f"(f));
    return u;
}

__device__ __forceinline__ uint32_t smem_u32(const void* p) {
    uint32_t a;
    asm("{ .reg .u64 t; cvta.to.shared.u64 t, %1; cvt.u32.u64 %0, t; }" : "=r"(a) : "l"(p));
    return a;
}

__device__ __forceinline__ void cp16(uint32_t dst, const void* src) {
    asm volatile("cp.async.cg.shared.global [%0], [%1], 16;" :: "r"(dst), "l"(src));
}

__device__ __forceinline__ void mma_tf32(float* d, const uint32_t* a, const uint32_t* b) {
    asm volatile(
        "mma.sync.aligned.m16n8k8.row.col.f32.tf32.tf32.f32 "
        "{%0,%1,%2,%3},{%4,%5,%6,%7},{%8,%9},{%0,%1,%2,%3};\n"
        : "+f"(d[0]), "+f"(d[1]), "+f"(d[2]), "+f"(d[3])
        : "r"(a[0]), "r"(a[1]), "r"(a[2]), "r"(a[3]), "r"(b[0]), "r"(b[1]));
}

__global__ void cvt_x_kernel(const float* __restrict__ x) {
    int i = blockIdx.x * blockDim.x + threadIdx.x;
    float4 v = reinterpret_cast<const float4*>(x)[i];
    uint4 o;
    o.x = f2tf32(v.x); o.y = f2tf32(v.y); o.z = f2tf32(v.z); o.w = f2tf32(v.w);
    reinterpret_cast<uint4*>(g_xt)[i] = o;
}

__global__ void combine_kernel(float* __restrict__ out) {
    int i = blockIdx.x * blockDim.x + threadIdx.x;
    float4 a = reinterpret_cast<const float4*>(g_part)[i];
    float4 b = reinterpret_cast<const float4*>(g_part + M_ROWS * N_COLS)[i];
    float4 v;
    v.x = a.x + b.x; v.y = a.y + b.y; v.z = a.z + b.z; v.w = a.w + b.w;
    reinterpret_cast<float4*>(out)[i] = v;
}

// partial[kh][m,n] = sum_{k in half kh} x[m,k]*W[n,k] + 2*s*B[n%16]*(x@A^T)_half[m, n/16]
__global__ __launch_bounds__(NTHR, 1)
void lokr_gemm_kernel(const float* __restrict__ Wm,
                      const float* __restrict__ Am,
                      const float* __restrict__ Bv,
                      const float* __restrict__ sc)
{
    extern __shared__ float sm[];
    const uint32_t sb = smem_u32(sm);

    const int t    = threadIdx.x;
    const int lane = t & 31;
    const int warp = t >> 5;
    const int wm   = warp & 3;          // 4 m-warps, 32 rows each
    const int wn   = (warp >> 2) & 1;   // 2 n-warps, 64 cols each
    const int wk   = warp >> 3;         // 2 k-warps, 4 kg each
    const int q    = lane & 3;
    const int g    = lane >> 2;
    const int n0   = blockIdx.x * BN;
    const int kh   = blockIdx.y;
    const size_t kb = (size_t)kh * KHALF;

    // ---- fill geometry: 16 f4-chunks per 64-float row ----
    const int kq = t & 15;
    const int rr = t >> 4;              // 0..31
    const int ar = (t >> 4) & 7;        // A row for t<128
    const uint32_t swb = (uint32_t)((kq ^ (rr & 7)) << 4);
    const float* xg = g_xt + (size_t)rr * K_DIM + kq * 4;
    const float* wg = Wm + (size_t)(n0 + rr) * K_DIM + kq * 4;
    const float* ag = Am + (size_t)(blockIdx.x * 8 + ar) * K_DIM + kq * 4;

    auto fill = [&](int f) {
        const int s = f % 3;
        const size_t ko = kb + (size_t)f * BK;
        #pragma unroll
        for (int j = 0; j < 4; ++j) {
            const uint32_t xd = sb + 4u * (XS_OFF + s * XSTG + (j * 32 + rr) * 64) + swb;
            cp16(xd, xg + (size_t)(32 * j) * K_DIM + ko);
            const uint32_t wd = sb + 4u * (WS_OFF + s * WSTG + (j * 32 + rr) * 64) + swb;
            cp16(wd, wg + (size_t)(32 * j) * K_DIM + ko);
        }
        if (t < 128) {
            const uint32_t ad = sb + 4u * (AS_OFF + s * ASTG + ar * 64 + ((kq ^ ar) << 2));
            cp16(ad, ag + ko);
        }
        asm volatile("cp.async.commit_group;");
    };

    fill(0);
    fill(1);

    float acc[2][8][4];   // mt x nt x 4
    float yac[2][4];
    #pragma unroll
    for (int mt = 0; mt < 2; ++mt) {
        #pragma unroll
        for (int nt = 0; nt < 8; ++nt)
            #pragma unroll
            for (int r = 0; r < 4; ++r) acc[mt][nt][r] = 0.0f;
        #pragma unroll
        for (int r = 0; r < 4; ++r) yac[mt][r] = 0.0f;
    }

    for (int kt = 0; kt < NKS; ++kt) {
        if (kt + 1 < NKS) asm volatile("cp.async.wait_group 1;");
        else              asm volatile("cp.async.wait_group 0;");
        __syncthreads();
        if (kt + 2 < NKS) fill(kt + 2);   // buf (kt+2)%3 == (kt-1)%3, drained by the barrier

        const int s = kt % 3;
        const float* xb = sm + XS_OFF + s * XSTG;
        const float* wb = sm + WS_OFF + s * WSTG;
        const float* ab = sm + AS_OFF + s * ASTG;

        #pragma unroll
        for (int kgl = 0; kgl < 4; ++kgl) {
            const int kg = wk * 4 + kgl;
            const int c0 = ((2 * kg) ^ g) * 4 + q;
            const int c1 = ((2 * kg + 1) ^ g) * 4 + q;
            uint32_t afr[2][4];
            #pragma unroll
            for (int mt = 0; mt < 2; ++mt) {
                const float* base = xb + (wm * 32 + mt * 16 + g) * 64;
                afr[mt][0] = __float_as_uint(base[c0]);
                afr[mt][1] = __float_as_uint(base[8 * 64 + c0]);
                afr[mt][2] = __float_as_uint(base[c1]);
                afr[mt][3] = __float_as_uint(base[8 * 64 + c1]);
            }
            uint32_t bfr[8][2];
            #pragma unroll
            for (int nt = 0; nt < 8; ++nt) {
                const float* bp = wb + (wn * 64 + nt * 8 + g) * 64;
                bfr[nt][0] = __float_as_uint(bp[c0]);
                bfr[nt][1] = __float_as_uint(bp[c1]);
            }
            uint32_t bex[2];
            {
                const float* ap = ab + g * 64;
                bex[0] = __float_as_uint(ap[c0]);
                bex[1] = __float_as_uint(ap[c1]);
            }
            #pragma unroll
            for (int mt = 0; mt < 2; ++mt) {
                #pragma unroll
                for (int nt = 0; nt < 8; ++nt)
                    mma_tf32(acc[mt][nt], afr[mt], bfr[nt]);
                mma_tf32(yac[mt], afr[mt], bex);
            }
        }
    }

    // ---- k-half reduction through smem scratch ----
    __syncthreads();
    float* scr = sm;
    if (wk == 1) {
        const int pos = warp - 8;
        float* p = scr + pos * 2336 + lane * 73;
        #pragma unroll
        for (int mt = 0; mt < 2; ++mt)
            #pragma unroll
            for (int nt = 0; nt < 8; ++nt)
                #pragma unroll
                for (int r = 0; r < 4; ++r)
                    p[(mt * 8 + nt) * 4 + r] = acc[mt][nt][r];
        #pragma unroll
        for (int mt = 0; mt < 2; ++mt)
            #pragma unroll
            for (int r = 0; r < 4; ++r)
                p[64 + mt * 4 + r] = yac[mt][r];
    }
    __syncthreads();
    if (wk == 0) {
        const float* p = scr + warp * 2336 + lane * 73;
        #pragma unroll
        for (int mt = 0; mt < 2; ++mt)
            #pragma unroll
            for (int nt = 0; nt < 8; ++nt)
                #pragma unroll
                for (int r = 0; r < 4; ++r)
                    acc[mt][nt][r] += p[(mt * 8 + nt) * 4 + r];
        #pragma unroll
        for (int mt = 0; mt < 2; ++mt)
            #pragma unroll
            for (int r = 0; r < 4; ++r)
                yac[mt][r] += p[64 + mt * 4 + r];

        // ---- epilogue to partial: out = acc + cf[n%16] * y[m, n/16] ----
        float* part = g_part + (size_t)kh * (M_ROWS * N_COLS);
        const float s2 = 2.0f * sc[0];
        const float cfe0 = s2 * Bv[2 * q];
        const float cfe1 = s2 * Bv[2 * q + 1];
        const float cfo0 = s2 * Bv[8 + 2 * q];
        const float cfo1 = s2 * Bv[9 + 2 * q];

        #pragma unroll
        for (int mt = 0; mt < 2; ++mt) {
            // y cols 4wn..4wn+3 live in lanes g*4 + (2wn) and g*4 + (2wn+1)
            const int L0 = g * 4 + 2 * wn;
            const float y00 = __shfl_sync(0xFFFFFFFFu, yac[mt][0], L0);      // y[g][4wn]
            const float y01 = __shfl_sync(0xFFFFFFFFu, yac[mt][1], L0);      // y[g][4wn+1]
            const float y02 = __shfl_sync(0xFFFFFFFFu, yac[mt][2], L0);      // y[g+8][4wn]
            const float y03 = __shfl_sync(0xFFFFFFFFu, yac[mt][3], L0);      // y[g+8][4wn+1]
            const float y10 = __shfl_sync(0xFFFFFFFFu, yac[mt][0], L0 + 1);  // y[g][4wn+2]
            const float y11 = __shfl_sync(0xFFFFFFFFu, yac[mt][1], L0 + 1);  // y[g][4wn+3]
            const float y12 = __shfl_sync(0xFFFFFFFFu, yac[mt][2], L0 + 1);  // y[g+8][4wn+2]
            const float y13 = __shfl_sync(0xFFFFFFFFu, yac[mt][3], L0 + 1);  // y[g+8][4wn+3]
            #pragma unroll
            for (int nt = 0; nt < 8; ++nt) {
                const int cc = nt >> 1;   // 0..3 -> A col (4wn + cc)
                const float yg  = (cc == 0) ? y00 : (cc == 1) ? y01 : (cc == 2) ? y10 : y11;
                const float yg8 = (cc == 0) ? y02 : (cc == 1) ? y03 : (cc == 2) ? y12 : y13;
                const float f0 = (nt & 1) ? cfo0 : cfe0;
                const float f1 = (nt & 1) ? cfo1 : cfe1;
                const int m = wm * 32 + mt * 16 + g;
                const int n = n0 + wn * 64 + nt * 8 + 2 * q;
                float2 v0 = make_float2(acc[mt][nt][0] + f0 * yg, acc[mt][nt][1] + f1 * yg);
                float2 v1 = make_float2(acc[mt][nt][2] + f0 * yg8, acc[mt][nt][3] + f1 * yg8);
                *reinterpret_cast<float2*>(part + (size_t)m * N_COLS + n) = v0;
                *reinterpret_cast<float2*>(part + (size_t)(m + 8) * N_COLS + n) = v1;
            }
        }
    }
}

extern "C" void kernel_launch(void* const* d_in, const int* in_sizes, int n_in,
                              void* d_out, int out_size) {
    const float* x  = (const float*)d_in[0];   // (128, 8192)
    const float* Wm = (const float*)d_in[1];   // (8192, 8192)
    const float* Am = (const float*)d_in[2];   // (512, 8192)
    const float* Bv = (const float*)d_in[3];   // (16, 1)
    const float* sc = (const float*)d_in[4];   // (1,)
    float* out = (float*)d_out;                // (128, 8192)

    cudaFuncSetAttribute(lokr_gemm_kernel,
                         cudaFuncAttributeMaxDynamicSharedMemorySize,
                         SMEM_FLOATS * 4);

    cvt_x_kernel<<<(M_ROWS * K_DIM / 4) / 256, 256>>>(x);
    dim3 grid(N_COLS / BN, 2);
    lokr_gemm_kernel<<<grid, NTHR, SMEM_FLOATS * 4>>>(Wm, Am, Bv, sc);
    combine_kernel<<<(M_ROWS * N_COLS / 4) / 256, 256>>>(out);
}

// round 10
// speedup vs baseline: 1.2327x; 1.0241x over previous
#include <cuda_runtime.h>
#include <cstdint>

#define K_DIM  8192
#define KHALF  4096
#define M_ROWS 128
#define N_COLS 8192
#define BM     128
#define BN     128
#define BK     64
#define NKS    (KHALF / BK)    // 64 stages per CTA
#define NBUF   3
#define NTHR   512

// smem floats per stage: x [128][64]; W [128][64]; A [8][64]; f4-xor swizzled rows
#define XSTG   (BM * BK)                      // 8192
#define WSTG   (BN * BK)                      // 8192
#define ASTG   (8 * BK)                       // 512
#define XS_OFF 0
#define WS_OFF (NBUF * XSTG)                  // 24576
#define AS_OFF (WS_OFF + NBUF * WSTG)         // 49152
#define SMEM_FLOATS (AS_OFF + NBUF * ASTG)    // 50688 floats = 202752 B

__device__ float g_part[2 * M_ROWS * N_COLS];     // split-K partials (8 MB)

__device__ __forceinline__ uint32_t smem_u32(const void* p) {
    uint32_t a;
    asm("{ .reg .u64 t; cvta.to.shared.u64 t, %1; cvt.u32.u64 %0, t; }" : "=r"(a) : "l"(p));
    return a;
}

__device__ __forceinline__ void cp16(uint32_t dst, const void* src) {
    asm volatile("cp.async.cg.shared.global [%0], [%1], 16;" :: "r"(dst), "l"(src));
}

__device__ __forceinline__ void mma_tf32(float* d, const uint32_t* a, const uint32_t* b) {
    asm volatile(
        "mma.sync.aligned.m16n8k8.row.col.f32.tf32.tf32.f32 "
        "{%0,%1,%2,%3},{%4,%5,%6,%7},{%8,%9},{%0,%1,%2,%3};\n"
        : "+f"(d[0]), "+f"(d[1]), "+f"(d[2]), "+f"(d[3])
        : "r"(a[0]), "r"(a[1]), "r"(a[2]), "r"(a[3]), "r"(b[0]), "r"(b[1]));
}

__global__ void combine_kernel(float* __restrict__ out) {
    int i = blockIdx.x * blockDim.x + threadIdx.x;
    float4 a = reinterpret_cast<const float4*>(g_part)[i];
    float4 b = reinterpret_cast<const float4*>(g_part + M_ROWS * N_COLS)[i];
    float4 v;
    v.x = a.x + b.x; v.y = a.y + b.y; v.z = a.z + b.z; v.w = a.w + b.w;
    reinterpret_cast<float4*>(out)[i] = v;
}

// partial[kh][m,n] = sum_{k in half kh} x[m,k]*W[n,k] + 2*s*B[n%16]*(x@A^T)_half[m, n/16]
// x, W, A all raw fp32 -> HW truncation to tf32 inside HMMA.
__global__ __launch_bounds__(NTHR, 1)
void lokr_gemm_kernel(const float* __restrict__ xm,
                      const float* __restrict__ Wm,
                      const float* __restrict__ Am,
                      const float* __restrict__ Bv,
                      const float* __restrict__ sc)
{
    extern __shared__ float sm[];
    const uint32_t sb = smem_u32(sm);

    const int t    = threadIdx.x;
    const int lane = t & 31;
    const int warp = t >> 5;
    const int wm   = warp & 3;          // 4 m-warps, 32 rows each
    const int wn   = (warp >> 2) & 1;   // 2 n-warps, 64 cols each
    const int wk   = warp >> 3;         // 2 k-warps, 4 kg each
    const int q    = lane & 3;
    const int g    = lane >> 2;
    const int n0   = blockIdx.x * BN;
    const int kh   = blockIdx.y;
    const size_t kb = (size_t)kh * KHALF;

    // ---- fill geometry: 16 f4-chunks per 64-float row ----
    const int kq = t & 15;
    const int rr = t >> 4;              // 0..31
    const int ar = (t >> 4) & 7;        // A row for t<128
    const uint32_t swb = (uint32_t)((kq ^ (rr & 7)) << 4);
    const float* xg = xm + (size_t)rr * K_DIM + kq * 4;
    const float* wg = Wm + (size_t)(n0 + rr) * K_DIM + kq * 4;
    const float* ag = Am + (size_t)(blockIdx.x * 8 + ar) * K_DIM + kq * 4;

    auto fill = [&](int f) {
        const int s = f % 3;
        const size_t ko = kb + (size_t)f * BK;
        #pragma unroll
        for (int j = 0; j < 4; ++j) {
            const uint32_t xd = sb + 4u * (XS_OFF + s * XSTG + (j * 32 + rr) * 64) + swb;
            cp16(xd, xg + (size_t)(32 * j) * K_DIM + ko);
            const uint32_t wd = sb + 4u * (WS_OFF + s * WSTG + (j * 32 + rr) * 64) + swb;
            cp16(wd, wg + (size_t)(32 * j) * K_DIM + ko);
        }
        if (t < 128) {
            const uint32_t ad = sb + 4u * (AS_OFF + s * ASTG + ar * 64 + ((kq ^ ar) << 2));
            cp16(ad, ag + ko);
        }
        asm volatile("cp.async.commit_group;");
    };

    fill(0);
    fill(1);

    float acc[2][8][4];   // mt x nt x 4
    float yac[2][4];
    #pragma unroll
    for (int mt = 0; mt < 2; ++mt) {
        #pragma unroll
        for (int nt = 0; nt < 8; ++nt)
            #pragma unroll
            for (int r = 0; r < 4; ++r) acc[mt][nt][r] = 0.0f;
        #pragma unroll
        for (int r = 0; r < 4; ++r) yac[mt][r] = 0.0f;
    }

    for (int kt = 0; kt < NKS; ++kt) {
        if (kt + 1 < NKS) asm volatile("cp.async.wait_group 1;");
        else              asm volatile("cp.async.wait_group 0;");
        __syncthreads();
        if (kt + 2 < NKS) fill(kt + 2);   // buf (kt+2)%3 == (kt-1)%3, drained by the barrier

        const int s = kt % 3;
        const float* xb = sm + XS_OFF + s * XSTG;
        const float* wb = sm + WS_OFF + s * WSTG;
        const float* ab = sm + AS_OFF + s * ASTG;

        #pragma unroll
        for (int kgl = 0; kgl < 4; ++kgl) {
            const int kg = wk * 4 + kgl;
            const int c0 = ((2 * kg) ^ g) * 4 + q;
            const int c1 = ((2 * kg + 1) ^ g) * 4 + q;
            uint32_t afr[2][4];
            #pragma unroll
            for (int mt = 0; mt < 2; ++mt) {
                const float* base = xb + (wm * 32 + mt * 16 + g) * 64;
                afr[mt][0] = __float_as_uint(base[c0]);
                afr[mt][1] = __float_as_uint(base[8 * 64 + c0]);
                afr[mt][2] = __float_as_uint(base[c1]);
                afr[mt][3] = __float_as_uint(base[8 * 64 + c1]);
            }
            uint32_t bfr[8][2];
            #pragma unroll
            for (int nt = 0; nt < 8; ++nt) {
                const float* bp = wb + (wn * 64 + nt * 8 + g) * 64;
                bfr[nt][0] = __float_as_uint(bp[c0]);
                bfr[nt][1] = __float_as_uint(bp[c1]);
            }
            uint32_t bex[2];
            {
                const float* ap = ab + g * 64;
                bex[0] = __float_as_uint(ap[c0]);
                bex[1] = __float_as_uint(ap[c1]);
            }
            #pragma unroll
            for (int mt = 0; mt < 2; ++mt) {
                #pragma unroll
                for (int nt = 0; nt < 8; ++nt)
                    mma_tf32(acc[mt][nt], afr[mt], bfr[nt]);
                mma_tf32(yac[mt], afr[mt], bex);
            }
        }
    }

    // ---- k-half reduction through smem scratch ----
    __syncthreads();
    float* scr = sm;
    if (wk == 1) {
        const int pos = warp - 8;
        float* p = scr + pos * 2336 + lane * 73;
        #pragma unroll
        for (int mt = 0; mt < 2; ++mt)
            #pragma unroll
            for (int nt = 0; nt < 8; ++nt)
                #pragma unroll
                for (int r = 0; r < 4; ++r)
                    p[(mt * 8 + nt) * 4 + r] = acc[mt][nt][r];
        #pragma unroll
        for (int mt = 0; mt < 2; ++mt)
            #pragma unroll
            for (int r = 0; r < 4; ++r)
                p[64 + mt * 4 + r] = yac[mt][r];
    }
    __syncthreads();
    if (wk == 0) {
        const float* p = scr + warp * 2336 + lane * 73;
        #pragma unroll
        for (int mt = 0; mt < 2; ++mt)
            #pragma unroll
            for (int nt = 0; nt < 8; ++nt)
                #pragma unroll
                for (int r = 0; r < 4; ++r)
                    acc[mt][nt][r] += p[(mt * 8 + nt) * 4 + r];
        #pragma unroll
        for (int mt = 0; mt < 2; ++mt)
            #pragma unroll
            for (int r = 0; r < 4; ++r)
                yac[mt][r] += p[64 + mt * 4 + r];

        // ---- epilogue to partial: out = acc + cf[n%16] * y[m, n/16] ----
        float* part = g_part + (size_t)kh * (M_ROWS * N_COLS);
        const float s2 = 2.0f * sc[0];
        const float cfe0 = s2 * Bv[2 * q];
        const float cfe1 = s2 * Bv[2 * q + 1];
        const float cfo0 = s2 * Bv[8 + 2 * q];
        const float cfo1 = s2 * Bv[9 + 2 * q];

        #pragma unroll
        for (int mt = 0; mt < 2; ++mt) {
            // y cols 4wn..4wn+3 live in lanes g*4 + (2wn) and g*4 + (2wn+1)
            const int L0 = g * 4 + 2 * wn;
            const float y00 = __shfl_sync(0xFFFFFFFFu, yac[mt][0], L0);
            const float y01 = __shfl_sync(0xFFFFFFFFu, yac[mt][1], L0);
            const float y02 = __shfl_sync(0xFFFFFFFFu, yac[mt][2], L0);
            const float y03 = __shfl_sync(0xFFFFFFFFu, yac[mt][3], L0);
            const float y10 = __shfl_sync(0xFFFFFFFFu, yac[mt][0], L0 + 1);
            const float y11 = __shfl_sync(0xFFFFFFFFu, yac[mt][1], L0 + 1);
            const float y12 = __shfl_sync(0xFFFFFFFFu, yac[mt][2], L0 + 1);
            const float y13 = __shfl_sync(0xFFFFFFFFu, yac[mt][3], L0 + 1);
            #pragma unroll
            for (int nt = 0; nt < 8; ++nt) {
                const int cc = nt >> 1;
                const float yg  = (cc == 0) ? y00 : (cc == 1) ? y01 : (cc == 2) ? y10 : y11;
                const float yg8 = (cc == 0) ? y02 : (cc == 1) ? y03 : (cc == 2) ? y12 : y13;
                const float f0 = (nt & 1) ? cfo0 : cfe0;
                const float f1 = (nt & 1) ? cfo1 : cfe1;
                const int m = wm * 32 + mt * 16 + g;
                const int n = n0 + wn * 64 + nt * 8 + 2 * q;
                float2 v0 = make_float2(acc[mt][nt][0] + f0 * yg, acc[mt][nt][1] + f1 * yg);
                float2 v1 = make_float2(acc[mt][nt][2] + f0 * yg8, acc[mt][nt][3] + f1 * yg8);
                *reinterpret_cast<float2*>(part + (size_t)m * N_COLS + n) = v0;
                *reinterpret_cast<float2*>(part + (size_t)(m + 8) * N_COLS + n) = v1;
            }
        }
    }
}

extern "C" void kernel_launch(void* const* d_in, const int* in_sizes, int n_in,
                              void* d_out, int out_size) {
    const float* x  = (const float*)d_in[0];   // (128, 8192)
    const float* Wm = (const float*)d_in[1];   // (8192, 8192)
    const float* Am = (const float*)d_in[2];   // (512, 8192)
    const float* Bv = (const float*)d_in[3];   // (16, 1)
    const float* sc = (const float*)d_in[4];   // (1,)
    float* out = (float*)d_out;                // (128, 8192)

    cudaFuncSetAttribute(lokr_gemm_kernel,
                         cudaFuncAttributeMaxDynamicSharedMemorySize,
                         SMEM_FLOATS * 4);

    dim3 grid(N_COLS / BN, 2);
    lokr_gemm_kernel<<<grid, NTHR, SMEM_FLOATS * 4>>>(x, Wm, Am, Bv, sc);
    combine_kernel<<<(M_ROWS * N_COLS / 4) / 256, 256>>>(out);
}